// round 8
// baseline (speedup 1.0000x reference)
#include <cuda_runtime.h>
#include <cstdint>

#define BB 32
#define CC 512
#define QQ 128
#define DD 768
#define NEGV (-1e30f)
#define FLOOR_F (-3.402823466e38f)

// ---------------- scratch (device globals) ---------------------------------
__device__ float g_S[BB * CC * QQ];        // similarity, 8 MB
__device__ float g_qT[BB * DD * QQ];       // q transposed [b][d][q], 12 MB
__device__ float g_Smax[BB * CC];          // max over q of S
__device__ float g_pmax[4 * BB * QQ];      // per-chunk column max
__device__ float g_psum[4 * BB * QQ];      // per-chunk column sum
__device__ float g_cdpart[4 * BB * DD];    // c_dash partials per c-chunk

// ---------------- helpers ---------------------------------------------------
__device__ __forceinline__ uint32_t f2tf(float f) {
    uint32_t r;
    asm("cvt.rna.tf32.f32 %0, %1;" : "=r"(r) : "f"(f));
    return r;
}

__device__ __forceinline__ void mma_tf32(float* c, const uint32_t* a,
                                         const uint32_t* b) {
    asm volatile(
        "mma.sync.aligned.m16n8k8.row.col.f32.tf32.tf32.f32 "
        "{%0,%1,%2,%3}, {%4,%5,%6,%7}, {%8,%9}, {%0,%1,%2,%3};"
        : "+f"(c[0]), "+f"(c[1]), "+f"(c[2]), "+f"(c[3])
        : "r"(a[0]), "r"(a[1]), "r"(a[2]), "r"(a[3]), "r"(b[0]), "r"(b[1]));
}

__device__ __forceinline__ uint32_t smem_u32(const void* p) {
    uint32_t a;
    asm("{ .reg .u64 t; cvta.to.shared.u64 t, %1; cvt.u32.u64 %0, t; }"
        : "=r"(a) : "l"(p));
    return a;
}

__device__ __forceinline__ void cp_async16(uint32_t dst, const void* src) {
    asm volatile("cp.async.cg.shared.global [%0], [%1], 16;"
                 :: "r"(dst), "l"(src));
}
#define CP_COMMIT() asm volatile("cp.async.commit_group;" ::: "memory")
#define CP_WAIT(n) asm volatile("cp.async.wait_group %0;" :: "n"(n) : "memory")

// ---------------- K1b: transpose q -> qT[b][d][q] --------------------------
__global__ void k_qtrans(const float* __restrict__ ques) {
    __shared__ float tile[32][33];
    int b = blockIdx.z;
    int q0 = blockIdx.x * 32;
    int d0 = blockIdx.y * 32;
    int lx = threadIdx.x, ly = threadIdx.y;
#pragma unroll
    for (int i = 0; i < 32; i += 8)
        tile[ly + i][lx] = ques[((size_t)b * QQ + q0 + ly + i) * DD + d0 + lx];
    __syncthreads();
#pragma unroll
    for (int i = 0; i < 32; i += 8)
        g_qT[((size_t)b * DD + d0 + ly + i) * QQ + q0 + lx] = tile[lx][ly + i];
}

// ---------------- k_sim helpers ---------------------------------------------
__device__ __forceinline__ void sim_ldg(const float* cbase, const float* qbase,
                                        int k0, int lrow, int lquad,
                                        float4 (&ar)[2][2], float4 (&br)[2][2]) {
#pragma unroll
    for (int r = 0; r < 2; r++) {
        int row = lrow + 64 * r;
#pragma unroll
        for (int cc = 0; cc < 2; cc++) {
            int col = k0 + lquad * 4 + 16 * cc;
            ar[r][cc] = *(const float4*)(cbase + (size_t)row * DD + col);
            br[r][cc] = *(const float4*)(qbase + (size_t)row * DD + col);
        }
    }
}

__device__ __forceinline__ void sim_sts(uint32_t* Adst, uint32_t* Bdst,
                                        const float* w1, const float* w2,
                                        const float* w3, int k0, int lrow,
                                        int lquad, float4 (&ar)[2][2],
                                        float4 (&br)[2][2], float* aacc,
                                        float* bqacc) {
#pragma unroll
    for (int cc = 0; cc < 2; cc++) {
        int col = lquad * 4 + 16 * cc;
        float4 w1v = *(const float4*)(w1 + k0 + col);
        float4 w2v = *(const float4*)(w2 + k0 + col);
        float4 w3v = *(const float4*)(w3 + k0 + col);
#pragma unroll
        for (int r = 0; r < 2; r++) {
            int row = lrow + 64 * r;
            float4 a = ar[r][cc], q = br[r][cc];
            aacc[r] += a.x * w1v.x + a.y * w1v.y + a.z * w1v.z + a.w * w1v.w;
            bqacc[r] += q.x * w2v.x + q.y * w2v.y + q.z * w2v.z + q.w * w2v.w;
            uint32_t* A = Adst + row * 36 + col;
            A[0] = f2tf(a.x); A[1] = f2tf(a.y);
            A[2] = f2tf(a.z); A[3] = f2tf(a.w);
            uint32_t* B = Bdst + row * 36 + col;
            B[0] = f2tf(q.x * w3v.x); B[1] = f2tf(q.y * w3v.y);
            B[2] = f2tf(q.z * w3v.z); B[3] = f2tf(q.w * w3v.w);
        }
    }
}

// ---------------- K2: similarity, fused rowdots + col stats ----------------
// grid (C/128, B), block 256 (8 warps 4x2). Tile 128x128, KT=32, dbl-buffered.
__global__ void __launch_bounds__(256) k_sim_mma(const float* __restrict__ cont,
                                                 const float* __restrict__ ques,
                                                 const float* __restrict__ SW,
                                                 const int* __restrict__ qmask) {
    extern __shared__ char sm[];
    uint32_t* Abuf = (uint32_t*)sm;                    // [2][128*36]
    uint32_t* Bbuf = Abuf + 2 * 128 * 36;              // [2][128*36]
    float* redm = (float*)(Bbuf + 2 * 128 * 36);       // [128][2]
    float* cmt_s = redm + 256;                         // [128]
    float* colm = cmt_s + 128;                         // [128][4]
    float* colsum = colm + 512;                        // [128][4]
    float* mC_s = colsum + 512;                        // [128]
    float* a_s = mC_s + 128;                           // [128]
    float* bq_s = a_s + 128;                           // [128]

    int t = threadIdx.x;
    int wid = t >> 5, lane = t & 31;
    int gp = lane >> 2, tq = lane & 3;
    int warp_m = wid & 3, warp_n = wid >> 2;
    int mbase = warp_m * 32, nbase = warp_n * 64;
    int b = blockIdx.y;
    int c0 = blockIdx.x * 128;

    if (t < QQ) cmt_s[t] = (1.0f - (float)qmask[b * QQ + t]) * NEGV;

    const float* cbase = cont + ((size_t)b * CC + c0) * DD;
    const float* qbase = ques + (size_t)b * QQ * DD;
    const float* w1 = SW;
    const float* w2 = SW + DD;
    const float* w3 = SW + 2 * DD;

    int lrow = t >> 2, lquad = t & 3;

    float acc[2][8][4];
#pragma unroll
    for (int mt = 0; mt < 2; mt++)
#pragma unroll
        for (int nt = 0; nt < 8; nt++)
#pragma unroll
            for (int j = 0; j < 4; j++) acc[mt][nt][j] = 0.f;
    float aacc[2] = {0.f, 0.f}, bqacc[2] = {0.f, 0.f};

    float4 ar[2][2], br[2][2];
    sim_ldg(cbase, qbase, 0, lrow, lquad, ar, br);
    sim_sts(Abuf, Bbuf, w1, w2, w3, 0, lrow, lquad, ar, br, aacc, bqacc);
    __syncthreads();

    for (int i = 0; i < 24; i++) {
        int cur = i & 1;
        if (i < 23) sim_ldg(cbase, qbase, 32 * (i + 1), lrow, lquad, ar, br);

        uint32_t* Au = Abuf + cur * (128 * 36);
        uint32_t* Bu = Bbuf + cur * (128 * 36);
#pragma unroll
        for (int ks = 0; ks < 4; ks++) {
            int kk = ks * 8;
            uint32_t aF[2][4];
#pragma unroll
            for (int mt = 0; mt < 2; mt++) {
                int mrow = mbase + mt * 16 + gp;
                aF[mt][0] = Au[mrow * 36 + kk + tq];
                aF[mt][1] = Au[(mrow + 8) * 36 + kk + tq];
                aF[mt][2] = Au[mrow * 36 + kk + tq + 4];
                aF[mt][3] = Au[(mrow + 8) * 36 + kk + tq + 4];
            }
            uint32_t bF[8][2];
#pragma unroll
            for (int nt = 0; nt < 8; nt++) {
                int nrow = nbase + nt * 8 + gp;
                bF[nt][0] = Bu[nrow * 36 + kk + tq];
                bF[nt][1] = Bu[nrow * 36 + kk + tq + 4];
            }
#pragma unroll
            for (int mt = 0; mt < 2; mt++)
#pragma unroll
                for (int nt = 0; nt < 8; nt++)
                    mma_tf32(acc[mt][nt], aF[mt], bF[nt]);
        }

        if (i < 23) {
            uint32_t* An = Abuf + (cur ^ 1) * (128 * 36);
            uint32_t* Bn = Bbuf + (cur ^ 1) * (128 * 36);
            sim_sts(An, Bn, w1, w2, w3, 32 * (i + 1), lrow, lquad, ar, br,
                    aacc, bqacc);
            __syncthreads();
        }
    }

    // finish fused row dots: reduce over the 4 lanes sharing a row
#pragma unroll
    for (int r = 0; r < 2; r++) {
        aacc[r] += __shfl_xor_sync(0xffffffffu, aacc[r], 1);
        aacc[r] += __shfl_xor_sync(0xffffffffu, aacc[r], 2);
        bqacc[r] += __shfl_xor_sync(0xffffffffu, bqacc[r], 1);
        bqacc[r] += __shfl_xor_sync(0xffffffffu, bqacc[r], 2);
    }
    if (lquad == 0) {
#pragma unroll
        for (int r = 0; r < 2; r++) {
            a_s[lrow + 64 * r] = aacc[r];
            bq_s[lrow + 64 * r] = bqacc[r];
        }
    }
    __syncthreads();

    // epilogue: s = acc + a + bq, write S, fused row max
#pragma unroll
    for (int mt = 0; mt < 2; mt++) {
        int rl0 = mbase + mt * 16 + gp;
        int rl1 = rl0 + 8;
        float a0v = a_s[rl0];
        float a1v = a_s[rl1];
        float m0 = FLOOR_F, m1 = FLOOR_F;
        float* S0 = g_S + ((size_t)b * CC + c0 + rl0) * QQ;
        float* S1 = g_S + ((size_t)b * CC + c0 + rl1) * QQ;
#pragma unroll
        for (int nt = 0; nt < 8; nt++) {
            int q = nbase + nt * 8 + 2 * tq;
            float bq0 = bq_s[q], bq1 = bq_s[q + 1];
            float s00 = acc[mt][nt][0] + a0v + bq0;
            float s01 = acc[mt][nt][1] + a0v + bq1;
            float s10 = acc[mt][nt][2] + a1v + bq0;
            float s11 = acc[mt][nt][3] + a1v + bq1;
            acc[mt][nt][0] = s00; acc[mt][nt][1] = s01;
            acc[mt][nt][2] = s10; acc[mt][nt][3] = s11;
            *(float2*)(S0 + q) = make_float2(s00, s01);
            *(float2*)(S1 + q) = make_float2(s10, s11);
            m0 = fmaxf(m0, fmaxf(s00, s01));
            m1 = fmaxf(m1, fmaxf(s10, s11));
        }
        m0 = fmaxf(m0, __shfl_xor_sync(0xffffffffu, m0, 1));
        m0 = fmaxf(m0, __shfl_xor_sync(0xffffffffu, m0, 2));
        m1 = fmaxf(m1, __shfl_xor_sync(0xffffffffu, m1, 1));
        m1 = fmaxf(m1, __shfl_xor_sync(0xffffffffu, m1, 2));
        if (tq == 0) {
            redm[rl0 * 2 + warp_n] = m0;
            redm[rl1 * 2 + warp_n] = m1;
        }
    }
    __syncthreads();
    if (t < 128)
        g_Smax[b * CC + c0 + t] = fmaxf(redm[t * 2], redm[t * 2 + 1]);

    // fused column softmax stats over this 128-c chunk (x = s + cmt)
    float xm[8][2];
#pragma unroll
    for (int nt = 0; nt < 8; nt++)
#pragma unroll
        for (int c2 = 0; c2 < 2; c2++) {
            int q = nbase + nt * 8 + 2 * tq + c2;
            float m = fmaxf(fmaxf(acc[0][nt][c2], acc[0][nt][2 + c2]),
                            fmaxf(acc[1][nt][c2], acc[1][nt][2 + c2]));
            xm[nt][c2] = m + cmt_s[q];
        }
#pragma unroll
    for (int o = 4; o <= 16; o <<= 1)
#pragma unroll
        for (int nt = 0; nt < 8; nt++)
#pragma unroll
            for (int c2 = 0; c2 < 2; c2++)
                xm[nt][c2] = fmaxf(xm[nt][c2],
                                   __shfl_xor_sync(0xffffffffu, xm[nt][c2], o));
    if (gp == 0) {
#pragma unroll
        for (int nt = 0; nt < 8; nt++)
#pragma unroll
            for (int c2 = 0; c2 < 2; c2++)
                colm[(nbase + nt * 8 + 2 * tq + c2) * 4 + warp_m] = xm[nt][c2];
    }
    __syncthreads();
    if (t < 128)
        mC_s[t] = fmaxf(fmaxf(colm[t * 4], colm[t * 4 + 1]),
                        fmaxf(colm[t * 4 + 2], colm[t * 4 + 3]));
    __syncthreads();

    float xs[8][2];
#pragma unroll
    for (int nt = 0; nt < 8; nt++)
#pragma unroll
        for (int c2 = 0; c2 < 2; c2++) {
            int q = nbase + nt * 8 + 2 * tq + c2;
            float mC = mC_s[q], cmt = cmt_s[q];
            xs[nt][c2] = __expf((acc[0][nt][c2] + cmt) - mC)
                       + __expf((acc[0][nt][2 + c2] + cmt) - mC)
                       + __expf((acc[1][nt][c2] + cmt) - mC)
                       + __expf((acc[1][nt][2 + c2] + cmt) - mC);
        }
#pragma unroll
    for (int o = 4; o <= 16; o <<= 1)
#pragma unroll
        for (int nt = 0; nt < 8; nt++)
#pragma unroll
            for (int c2 = 0; c2 < 2; c2++)
                xs[nt][c2] += __shfl_xor_sync(0xffffffffu, xs[nt][c2], o);
    if (gp == 0) {
#pragma unroll
        for (int nt = 0; nt < 8; nt++)
#pragma unroll
            for (int c2 = 0; c2 < 2; c2++)
                colsum[(nbase + nt * 8 + 2 * tq + c2) * 4 + warp_m] = xs[nt][c2];
    }
    __syncthreads();
    if (t < 128) {
        int idx = (blockIdx.x * BB + b) * QQ + t;
        g_pmax[idx] = mC_s[t];
        g_psum[idx] = (colsum[t * 4] + colsum[t * 4 + 1]) +
                      (colsum[t * 4 + 2] + colsum[t * 4 + 3]);
    }
}

// ---------------- K_cdash: partials over c-chunks --------------------------
// grid (B, D/128, 4), block 128
__global__ void __launch_bounds__(128) k_cdash_part(const float* __restrict__ cont,
                                                    const int* __restrict__ cmask) {
    __shared__ float es[128];
    __shared__ float red[128];
    int b = blockIdx.x;
    int d0 = blockIdx.y * 128;
    int chunk = blockIdx.z;
    int t = threadIdx.x;

    float xv[4];
    float lm = FLOOR_F;
#pragma unroll
    for (int r = 0; r < 4; r++) {
        int c = t + 128 * r;
        float x = g_Smax[b * CC + c] + (1.0f - (float)cmask[b * CC + c]) * NEGV;
        xv[r] = x;
        lm = fmaxf(lm, x);
    }
    red[t] = lm;
    __syncthreads();
    for (int o = 64; o; o >>= 1) {
        if (t < o) red[t] = fmaxf(red[t], red[t + o]);
        __syncthreads();
    }
    float m = red[0];
    __syncthreads();
    float lsum = 0.f;
#pragma unroll
    for (int r = 0; r < 4; r++) lsum += __expf(xv[r] - m);
    red[t] = lsum;
    __syncthreads();
    for (int o = 64; o; o >>= 1) {
        if (t < o) red[t] += red[t + o];
        __syncthreads();
    }
    float inv = 1.0f / red[0];
    __syncthreads();
    es[t] = __expf(xv[chunk] - m) * inv;
    __syncthreads();

    int d = d0 + t;
    const float* cb = cont + ((size_t)b * CC + (size_t)chunk * 128) * DD + d;
    float a0 = 0.f, a1 = 0.f, a2 = 0.f, a3 = 0.f;
    for (int c = 0; c < 128; c += 4) {
        a0 += es[c + 0] * cb[(size_t)(c + 0) * DD];
        a1 += es[c + 1] * cb[(size_t)(c + 1) * DD];
        a2 += es[c + 2] * cb[(size_t)(c + 2) * DD];
        a3 += es[c + 3] * cb[(size_t)(c + 3) * DD];
    }
    g_cdpart[((size_t)chunk * BB + b) * DD + d] = (a0 + a1) + (a2 + a3);
}

// ---------------- K4: c2q = P @ qT, persistent P, cp.async Q pipeline ------
// grid (C/128, B), block 256.
__global__ void __launch_bounds__(256) k_out_mma(const float* __restrict__ cont,
                                                 const int* __restrict__ qmask,
                                                 float* __restrict__ out) {
    extern __shared__ char sm[];
    uint32_t* Ps = (uint32_t*)sm;                         // [128*132] tf32
    float* Qs = (float*)(sm + 128 * 132 * 4);             // [2][128*132] f32
    float* cm_s = (float*)(sm + 3 * 128 * 132 * 4);       // [128]
    float* ci_s = cm_s + 128;
    float* cmt_s = ci_s + 128;
    float* cd_s = cmt_s + 128;

    int t = threadIdx.x;
    int wid = t >> 5, lane = t & 31;
    int gp = lane >> 2, tq = lane & 3;
    int warp_m = wid & 3, warp_n = wid >> 2;
    int mbase = warp_m * 32, nbase = warp_n * 64;
    int b = blockIdx.y;
    int c0 = blockIdx.x * 128;

    // prologue: combine per-chunk column stats -> cm/ci (was k_colcombine)
    if (t < 128) {
        cmt_s[t] = (1.0f - (float)qmask[b * QQ + t]) * NEGV;
        float pm[4];
#pragma unroll
        for (int ch = 0; ch < 4; ch++) pm[ch] = g_pmax[(ch * BB + b) * QQ + t];
        float m = pm[0];
#pragma unroll
        for (int ch = 1; ch < 4; ch++) m = fmaxf(m, pm[ch]);
        float s = 0.f;
#pragma unroll
        for (int ch = 0; ch < 4; ch++)
            s += g_psum[(ch * BB + b) * QQ + t] * __expf(pm[ch] - m);
        cm_s[t] = m;
        ci_s[t] = 1.0f / s;
    }
    __syncthreads();

    // build P tile once: P = exp((s + cmt) - cm) * ci, tf32
    int lrow = t >> 2, lq4 = (t & 3) * 4;
#pragma unroll
    for (int r = 0; r < 2; r++) {
        int row = lrow + 64 * r;
        const float* Srow = g_S + ((size_t)b * CC + c0 + row) * QQ;
#pragma unroll
        for (int kc = 0; kc < 8; kc++) {
            int col = kc * 16 + lq4;
            float4 s = *(const float4*)(Srow + col);
            float4 mt4 = *(const float4*)(cmt_s + col);
            float4 cm4 = *(const float4*)(cm_s + col);
            float4 ci4 = *(const float4*)(ci_s + col);
            uint4 v;
            v.x = f2tf(__expf((s.x + mt4.x) - cm4.x) * ci4.x);
            v.y = f2tf(__expf((s.y + mt4.y) - cm4.y) * ci4.y);
            v.z = f2tf(__expf((s.z + mt4.z) - cm4.z) * ci4.z);
            v.w = f2tf(__expf((s.w + mt4.w) - cm4.w) * ci4.w);
            *(uint4*)(Ps + row * 132 + col) = v;
        }
    }

    uint32_t qs_base = smem_u32(Qs);
    const float* qT_b = g_qT + (size_t)b * DD * QQ;

    // issue Q tile 0
#pragma unroll
    for (int r = 0; r < 2; r++) {
        int row = lrow + 64 * r;
#pragma unroll
        for (int kc = 0; kc < 8; kc++) {
            int col = kc * 16 + lq4;
            cp_async16(qs_base + (row * 132 + col) * 4,
                       qT_b + (size_t)row * QQ + col);
        }
    }
    CP_COMMIT();

    for (int dt = 0; dt < 6; dt++) {
        int cur = dt & 1;
        if (dt < 5) {
            uint32_t nb = qs_base + (cur ^ 1) * (128 * 132 * 4);
            const float* src = qT_b + (size_t)(dt + 1) * 128 * QQ;
#pragma unroll
            for (int r = 0; r < 2; r++) {
                int row = lrow + 64 * r;
#pragma unroll
                for (int kc = 0; kc < 8; kc++) {
                    int col = kc * 16 + lq4;
                    cp_async16(nb + (row * 132 + col) * 4,
                               src + (size_t)row * QQ + col);
                }
            }
            CP_COMMIT();
            CP_WAIT(1);
        } else {
            CP_WAIT(0);
        }
        // cd for this d-tile: sum the 4 partials (was k_cdcombine)
        if (t < 128) {
            int d = dt * 128 + t;
            float p0 = g_cdpart[((size_t)0 * BB + b) * DD + d];
            float p1 = g_cdpart[((size_t)1 * BB + b) * DD + d];
            float p2 = g_cdpart[((size_t)2 * BB + b) * DD + d];
            float p3 = g_cdpart[((size_t)3 * BB + b) * DD + d];
            cd_s[t] = (p0 + p1) + (p2 + p3);
        }
        __syncthreads();

        const float* Qu = Qs + cur * (128 * 132);
        float acc[2][8][4];
#pragma unroll
        for (int mt = 0; mt < 2; mt++)
#pragma unroll
            for (int nt = 0; nt < 8; nt++)
#pragma unroll
                for (int j = 0; j < 4; j++) acc[mt][nt][j] = 0.f;

#pragma unroll 4
        for (int ks = 0; ks < 16; ks++) {
            int kk = ks * 8;
            uint32_t aF[2][4];
#pragma unroll
            for (int mt = 0; mt < 2; mt++) {
                int mrow = mbase + mt * 16 + gp;
                aF[mt][0] = Ps[mrow * 132 + kk + tq];
                aF[mt][1] = Ps[(mrow + 8) * 132 + kk + tq];
                aF[mt][2] = Ps[mrow * 132 + kk + tq + 4];
                aF[mt][3] = Ps[(mrow + 8) * 132 + kk + tq + 4];
            }
            uint32_t bF[8][2];
#pragma unroll
            for (int nt = 0; nt < 8; nt++) {
                int nrow = nbase + nt * 8 + gp;
                bF[nt][0] = f2tf(Qu[nrow * 132 + kk + tq]);
                bF[nt][1] = f2tf(Qu[nrow * 132 + kk + tq + 4]);
            }
#pragma unroll
            for (int mt = 0; mt < 2; mt++)
#pragma unroll
                for (int nt = 0; nt < 8; nt++)
                    mma_tf32(acc[mt][nt], aF[mt], bF[nt]);
        }

        int d0 = dt * 128;
        // epilogue: out = [c | c2q | c*c2q | c*c_dash]
#pragma unroll
        for (int mt = 0; mt < 2; mt++) {
#pragma unroll
            for (int half = 0; half < 2; half++) {
                int rl = mbase + mt * 16 + gp + half * 8;
                size_t crow = (size_t)b * CC + c0 + rl;
                const float* crp = cont + crow * DD;
                float* orp = out + crow * (4 * DD);
#pragma unroll
                for (int nt = 0; nt < 8; nt++) {
                    int dloc = nbase + nt * 8 + 2 * tq;
                    int dcol = d0 + dloc;
                    float c2q0 = acc[mt][nt][half * 2 + 0];
                    float c2q1 = acc[mt][nt][half * 2 + 1];
                    float2 cv = *(const float2*)(crp + dcol);
                    float cd0 = cd_s[dloc], cd1 = cd_s[dloc + 1];
                    *(float2*)(orp + dcol) = cv;
                    *(float2*)(orp + DD + dcol) = make_float2(c2q0, c2q1);
                    *(float2*)(orp + 2 * DD + dcol) =
                        make_float2(cv.x * c2q0, cv.y * c2q1);
                    *(float2*)(orp + 3 * DD + dcol) =
                        make_float2(cv.x * cd0, cv.y * cd1);
                }
            }
        }
        __syncthreads();
    }
}

// ---------------- launch ---------------------------------------------------
extern "C" void kernel_launch(void* const* d_in, const int* in_sizes, int n_in,
                              void* d_out, int out_size) {
    const float* cont = (const float*)d_in[0];   // (32,512,768) f32
    const int* cmask = (const int*)d_in[1];      // (32,512) i32
    const float* ques = (const float*)d_in[2];   // (32,128,768) f32
    const int* qmask = (const int*)d_in[3];      // (32,128) i32
    const float* SW = (const float*)d_in[4];     // (2304,) f32
    float* out = (float*)d_out;                  // (32,512,3072) f32

    const int SIM_SMEM = 4 * 128 * 36 * 4 + (256 + 128 + 512 + 512 + 128 + 128 + 128) * 4;
    const int OUT_SMEM = 3 * 128 * 132 * 4 + 4 * 128 * 4;
    cudaFuncSetAttribute(k_sim_mma, cudaFuncAttributeMaxDynamicSharedMemorySize,
                         SIM_SMEM);
    cudaFuncSetAttribute(k_out_mma, cudaFuncAttributeMaxDynamicSharedMemorySize,
                         OUT_SMEM);

    k_qtrans<<<dim3(QQ / 32, DD / 32, BB), dim3(32, 8)>>>(ques);
    k_sim_mma<<<dim3(CC / 128, BB), 256, SIM_SMEM>>>(cont, ques, SW, qmask);
    k_cdash_part<<<dim3(BB, DD / 128, 4), 128>>>(cont, cmask);
    k_out_mma<<<dim3(CC / 128, BB), 256, OUT_SMEM>>>(cont, qmask, out);
}